// round 15
// baseline (speedup 1.0000x reference)
#include <cuda_runtime.h>
#include <cuda_bf16.h>

#define NN   50000
#define EE   800000
#define CH   128
#define NB   256
#define NCLS 10
#define MLPH 64
#define EPSV 1e-5f

#define SCAN_BLK 512
#define NBLK ((NN + SCAN_BLK - 1) / SCAN_BLK)   // 98

// padded row length for bf16 tiles: 136 elements (272B) -> conflict-free ldmatrix
#define LDK 136
#define WIMG_U32 (CH * LDK / 2)

// ---------------- scratch ----------------
__device__ float    g_deg[NN];
__device__ int      g_degcnt[NN];
__device__ int      g_rowptr[NN + 1];
__device__ int      g_woff[NN];
__device__ int      g_bsum[NBLK];
__device__ int      g_boff[NBLK];
__device__ int      g_csr_src[EE];
__device__ float    g_csr_norm[EE];
__device__ float    g_hlin[NN * CH];
__device__ float    g_hbuf[NN * CH];
__device__ float    g_chsum[CH];
__device__ float    g_chsq[CH];
__device__ float    g_gsum[NB * CH];
__device__ float    g_gcnt[NB];
__device__ unsigned g_Wimg_hi[3][WIMG_U32];
__device__ unsigned g_Wimg_lo[3][WIMG_U32];

// ---------------- mma helpers ----------------
__device__ __forceinline__ unsigned smem_u32(const void* p) {
    unsigned a;
    asm("{ .reg .u64 t; cvta.to.shared.u64 t, %1; cvt.u32.u64 %0, t; }" : "=r"(a) : "l"(p));
    return a;
}
__device__ __forceinline__ void ldsm_x4(unsigned* r, unsigned addr) {
    asm volatile("ldmatrix.sync.aligned.m8n8.x4.shared.b16 {%0,%1,%2,%3}, [%4];"
                 : "=r"(r[0]), "=r"(r[1]), "=r"(r[2]), "=r"(r[3]) : "r"(addr));
}
__device__ __forceinline__ void mma16816(float* c, const unsigned* a, unsigned b0, unsigned b1) {
    asm volatile(
        "mma.sync.aligned.m16n8k16.row.col.f32.bf16.bf16.f32 "
        "{%0,%1,%2,%3}, {%4,%5,%6,%7}, {%8,%9}, {%0,%1,%2,%3};"
        : "+f"(c[0]), "+f"(c[1]), "+f"(c[2]), "+f"(c[3])
        : "r"(a[0]), "r"(a[1]), "r"(a[2]), "r"(a[3]), "r"(b0), "r"(b1));
}
__device__ __forceinline__ unsigned pack_bf16_hi(float a0, float a1, unsigned* lo) {
    __nv_bfloat16 h0 = __float2bfloat16(a0);
    __nv_bfloat16 h1 = __float2bfloat16(a1);
    __nv_bfloat16 l0 = __float2bfloat16(a0 - __bfloat162float(h0));
    __nv_bfloat16 l1 = __float2bfloat16(a1 - __bfloat162float(h1));
    *lo = (unsigned)__bfloat16_as_ushort(l0) | ((unsigned)__bfloat16_as_ushort(l1) << 16);
    return (unsigned)__bfloat16_as_ushort(h0) | ((unsigned)__bfloat16_as_ushort(h1) << 16);
}

#define TILE_B (CH * LDK * 2)
#define SM_AHI 0
#define SM_ALO TILE_B
#define SM_WHI (2 * TILE_B)
#define SM_WLO (3 * TILE_B)
#define SM_TOTAL (4 * TILE_B)

// ---------------- W split precompute, all 3 layers in one launch ----------------
__global__ void wconv_kernel(const float* __restrict__ W1, const float* __restrict__ W2,
                             const float* __restrict__ W3) {
    int g = blockIdx.x * blockDim.x + threadIdx.x;
    int layer = g / (CH * CH / 2);
    int r = g % (CH * CH / 2);
    if (layer >= 3) return;
    const float* W = (layer == 0) ? W1 : (layer == 1) ? W2 : W3;
    int n = r >> 6;
    int kp = (r & 63) * 2;
    float a0 = W[kp * CH + n];
    float a1 = W[(kp + 1) * CH + n];
    unsigned lo;
    unsigned hi = pack_bf16_hi(a0, a1, &lo);
    int idx = (n * LDK + kp) / 2;
    g_Wimg_hi[layer][idx] = hi;
    g_Wimg_lo[layer][idx] = lo;
}

// ---------------- HMMA GEMM: 128x128 tile/CTA, split-bf16 3 products ----------------
__global__ void __launch_bounds__(256, 1) gemm_mma_kernel(const float* __restrict__ A, int layer) {
    extern __shared__ char smem[];
    unsigned sb = smem_u32(smem);
    int tid = threadIdx.x;
    int wid = tid >> 5;
    int lane = tid & 31;
    int row0 = blockIdx.x * 128;

    {
        const uint4* wh = (const uint4*)g_Wimg_hi[layer];
        const uint4* wl = (const uint4*)g_Wimg_lo[layer];
        for (int i = tid; i < TILE_B / 16; i += 256) {
            *(uint4*)(smem + SM_WHI + i * 16) = wh[i];
            *(uint4*)(smem + SM_WLO + i * 16) = wl[i];
        }
    }
    {
        int r = tid >> 1;
        int k0 = (tid & 1) * 64;
        int row = row0 + r;
        unsigned* dh = (unsigned*)(smem + SM_AHI) + (r * LDK + k0) / 2;
        unsigned* dl = (unsigned*)(smem + SM_ALO) + (r * LDK + k0) / 2;
        if (row < NN) {
            const float* ap = &A[row * CH + k0];
#pragma unroll
            for (int i = 0; i < 16; i++) {
                float4 v = *(const float4*)&ap[i * 4];
                unsigned lo0, lo1;
                unsigned hi0 = pack_bf16_hi(v.x, v.y, &lo0);
                unsigned hi1 = pack_bf16_hi(v.z, v.w, &lo1);
                dh[i * 2] = hi0; dh[i * 2 + 1] = hi1;
                dl[i * 2] = lo0; dl[i * 2 + 1] = lo1;
            }
        } else {
#pragma unroll
            for (int i = 0; i < 32; i++) { dh[i] = 0u; dl[i] = 0u; }
        }
    }
    __syncthreads();

    int wm0 = (wid >> 1) * 32;
    int wn0 = (wid & 1) * 64;

    float c[2][8][4];
#pragma unroll
    for (int mt = 0; mt < 2; mt++)
#pragma unroll
        for (int nt = 0; nt < 8; nt++)
#pragma unroll
            for (int j = 0; j < 4; j++) c[mt][nt][j] = 0.f;

    int rsel = lane & 15;
    int ksel = (lane >> 4) * 8;

#pragma unroll
    for (int ch = 0; ch < 8; ch++) {
        int k0 = ch * 16;
        unsigned ahi[2][4], alo[2][4];
#pragma unroll
        for (int mt = 0; mt < 2; mt++) {
            unsigned aaddr = sb + SM_AHI + ((wm0 + mt * 16 + rsel) * LDK + k0 + ksel) * 2;
            ldsm_x4(ahi[mt], aaddr);
            ldsm_x4(alo[mt], aaddr + (SM_ALO - SM_AHI));
        }
#pragma unroll
        for (int nb = 0; nb < 4; nb++) {
            unsigned baddr = sb + SM_WHI + ((wn0 + nb * 16 + rsel) * LDK + k0 + ksel) * 2;
            unsigned bh[4], bl[4];
            ldsm_x4(bh, baddr);
            ldsm_x4(bl, baddr + (SM_WLO - SM_WHI));
#pragma unroll
            for (int mt = 0; mt < 2; mt++) {
                mma16816(c[mt][nb * 2],     ahi[mt], bh[0], bh[2]);
                mma16816(c[mt][nb * 2],     alo[mt], bh[0], bh[2]);
                mma16816(c[mt][nb * 2],     ahi[mt], bl[0], bl[2]);
                mma16816(c[mt][nb * 2 + 1], ahi[mt], bh[1], bh[3]);
                mma16816(c[mt][nb * 2 + 1], alo[mt], bh[1], bh[3]);
                mma16816(c[mt][nb * 2 + 1], ahi[mt], bl[1], bl[3]);
            }
        }
    }

    int lrow = lane >> 2;
    int lcol = (lane & 3) * 2;
#pragma unroll
    for (int mt = 0; mt < 2; mt++) {
        int r1 = row0 + wm0 + mt * 16 + lrow;
        int r2 = r1 + 8;
#pragma unroll
        for (int nt = 0; nt < 8; nt++) {
            int col = wn0 + nt * 8 + lcol;
            if (r1 < NN) *(float2*)&g_hlin[r1 * CH + col] = make_float2(c[mt][nt][0], c[mt][nt][1]);
            if (r2 < NN) *(float2*)&g_hlin[r2 * CH + col] = make_float2(c[mt][nt][2], c[mt][nt][3]);
        }
    }
}

// ---------------- init ----------------
__global__ void init_kernel() {
    int i = blockIdx.x * blockDim.x + threadIdx.x;
    if (i < NN) { g_deg[i] = 1.0f; g_degcnt[i] = 0; }
    if (i < CH) { g_chsum[i] = 0.f; g_chsq[i] = 0.f; }
    if (i < NB * CH) g_gsum[i] = 0.f;
    if (i < NB) g_gcnt[i] = 0.f;
}

__global__ void deg_kernel(const int* __restrict__ dst, const float* __restrict__ ew) {
    int e = blockIdx.x * blockDim.x + threadIdx.x;
    if (e < EE) {
        int d = dst[e];
        atomicAdd(&g_deg[d], ew[e]);
        atomicAdd(&g_degcnt[d], 1);
    }
}

// blocksum + dinv fused
__global__ void blocksum_kernel() {
    __shared__ int ws[SCAN_BLK / 32];
    int t = threadIdx.x;
    int i = blockIdx.x * SCAN_BLK + t;
    if (i < NN) g_deg[i] = rsqrtf(g_deg[i]);
    int v = (i < NN) ? g_degcnt[i] : 0;
#pragma unroll
    for (int o = 16; o > 0; o >>= 1) v += __shfl_down_sync(0xffffffffu, v, o);
    if ((t & 31) == 0) ws[t >> 5] = v;
    __syncthreads();
    if (t < 32) {
        int s = (t < SCAN_BLK / 32) ? ws[t] : 0;
#pragma unroll
        for (int o = 16; o > 0; o >>= 1) s += __shfl_down_sync(0xffffffffu, s, o);
        if (t == 0) g_bsum[blockIdx.x] = s;
    }
}

__global__ void bscan_kernel() {
    __shared__ int sh[128];
    int t = threadIdx.x;
    sh[t] = (t < NBLK) ? g_bsum[t] : 0;
    __syncthreads();
#pragma unroll
    for (int o = 1; o < 128; o <<= 1) {
        int v = (t >= o) ? sh[t - o] : 0;
        __syncthreads();
        sh[t] += v;
        __syncthreads();
    }
    if (t < NBLK) g_boff[t] = sh[t] - g_bsum[t];
}

// rowptr + per-graph count fused
__global__ void rowptr_kernel(const int* __restrict__ batch) {
    __shared__ int ws[SCAN_BLK / 32];
    int t = threadIdx.x;
    int i = blockIdx.x * SCAN_BLK + t;
    if (i < NN) atomicAdd(&g_gcnt[batch[i]], 1.0f);
    int v = (i < NN) ? g_degcnt[i] : 0;
    int lane = t & 31;
    int wid = t >> 5;
    int sc = v;
#pragma unroll
    for (int o = 1; o < 32; o <<= 1) {
        int u = __shfl_up_sync(0xffffffffu, sc, o);
        if (lane >= o) sc += u;
    }
    if (lane == 31) ws[wid] = sc;
    __syncthreads();
    if (t < 32) {
        int s = (t < SCAN_BLK / 32) ? ws[t] : 0;
#pragma unroll
        for (int o = 1; o < 32; o <<= 1) {
            int u = __shfl_up_sync(0xffffffffu, s, o);
            if ((t & 31) >= o) s += u;
        }
        if (t < SCAN_BLK / 32) ws[t] = s;
    }
    __syncthreads();
    int excl = sc - v + ((wid > 0) ? ws[wid - 1] : 0) + g_boff[blockIdx.x];
    if (i < NN) { g_rowptr[i] = excl; g_woff[i] = excl; }
    if (i == NN - 1) g_rowptr[NN] = EE;
}

__global__ void fill_kernel(const int* __restrict__ src, const int* __restrict__ dst,
                            const float* __restrict__ ew) {
    int e = blockIdx.x * blockDim.x + threadIdx.x;
    if (e >= EE) return;
    int s = src[e];
    int d = dst[e];
    float nm = g_deg[s] * ew[e] * g_deg[d];
    int pos = atomicAdd(&g_woff[d], 1);
    g_csr_src[pos] = s;
    g_csr_norm[pos] = nm;
}

// ---------------- aggregation: warp per dst node, 2-way edge ILP ----------------
__global__ void agg_kernel(const float* __restrict__ bias) {
    int gid = blockIdx.x * blockDim.x + threadIdx.x;
    int n = gid >> 5;
    if (n >= NN) return;
    int lane = gid & 31;

    float di = g_deg[n];
    float d2 = di * di;
    float4 self = *(const float4*)&g_hlin[n * CH + lane * 4];
    float4 acc = make_float4(self.x * d2, self.y * d2, self.z * d2, self.w * d2);
    float4 acc2 = make_float4(0.f, 0.f, 0.f, 0.f);

    int beg = g_rowptr[n];
    int end = g_rowptr[n + 1];
    int p = beg;

    // peel to even count
    if ((end - beg) & 1) {
        int s = __ldg(&g_csr_src[p]);
        float nm = __ldg(&g_csr_norm[p]);
        float4 v = *(const float4*)&g_hlin[s * CH + lane * 4];
        acc.x += nm * v.x; acc.y += nm * v.y; acc.z += nm * v.z; acc.w += nm * v.w;
        p++;
    }
    // 2 independent edges per iteration: index loads batched, gathers independent
    for (; p < end; p += 2) {
        int sA = __ldg(&g_csr_src[p]);
        int sB = __ldg(&g_csr_src[p + 1]);
        float nA = __ldg(&g_csr_norm[p]);
        float nB = __ldg(&g_csr_norm[p + 1]);
        float4 vA = *(const float4*)&g_hlin[sA * CH + lane * 4];
        float4 vB = *(const float4*)&g_hlin[sB * CH + lane * 4];
        acc.x  += nA * vA.x; acc.y  += nA * vA.y; acc.z  += nA * vA.z; acc.w  += nA * vA.w;
        acc2.x += nB * vB.x; acc2.y += nB * vB.y; acc2.z += nB * vB.z; acc2.w += nB * vB.w;
    }
    acc.x += acc2.x; acc.y += acc2.y; acc.z += acc2.z; acc.w += acc2.w;

    float4 b = *(const float4*)&bias[lane * 4];
    float4 r;
    r.x = fmaxf(acc.x + b.x, 0.f);
    r.y = fmaxf(acc.y + b.y, 0.f);
    r.z = fmaxf(acc.z + b.z, 0.f);
    r.w = fmaxf(acc.w + b.w, 0.f);
    *(float4*)&g_hbuf[n * CH + lane * 4] = r;
}

// ---------------- BN stats + pooled sums ----------------
#define NPB 256
__global__ void pool_kernel(const int* __restrict__ batch) {
    int c = threadIdx.x;
    int n0 = blockIdx.x * NPB;
    int nend = min(n0 + NPB, NN);
    if (n0 >= NN) return;
    float s = 0.f, sq = 0.f, loc = 0.f;
    int curg = __ldg(&batch[n0]);
    for (int n = n0; n < nend; n++) {
        float v = g_hbuf[n * CH + c];
        s += v; sq += v * v;
        int g = __ldg(&batch[n]);
        if (g != curg) {
            atomicAdd(&g_gsum[curg * CH + c], loc);
            loc = 0.f;
            curg = g;
        }
        loc += v;
    }
    atomicAdd(&g_gsum[curg * CH + c], loc);
    atomicAdd(&g_chsum[c], s);
    atomicAdd(&g_chsq[c], sq);
}

// ---------------- head ----------------
__global__ void head_kernel(const float* __restrict__ gamma, const float* __restrict__ beta,
                            const float* __restrict__ Wm1, const float* __restrict__ bm1,
                            const float* __restrict__ Wm2, const float* __restrict__ bm2,
                            float* __restrict__ out) {
    __shared__ float gs[CH];
    __shared__ float tt[MLPH];
    int b = blockIdx.x;
    int c = threadIdx.x;
    float mu = g_chsum[c] * (1.0f / NN);
    float var = g_chsq[c] * (1.0f / NN) - mu * mu;
    float rs = rsqrtf(var + EPSV);
    float cnt = fmaxf(g_gcnt[b], 1.0f);
    gs[c] = (g_gsum[b * CH + c] / cnt - mu) * rs * gamma[c] + beta[c];
    __syncthreads();
    if (c < MLPH) {
        float acc = bm1[c];
#pragma unroll 8
        for (int k = 0; k < CH; k++) acc += gs[k] * Wm1[k * MLPH + c];
        tt[c] = acc;
    }
    __syncthreads();
    if (c < NCLS) {
        float acc = bm2[c];
#pragma unroll 8
        for (int k = 0; k < MLPH; k++) acc += tt[k] * Wm2[k * NCLS + c];
        out[b * NCLS + c] = acc;
    }
}

// ---------------- launch ----------------
extern "C" void kernel_launch(void* const* d_in, const int* in_sizes, int n_in,
                              void* d_out, int out_size) {
    const float* x     = (const float*)d_in[0];
    const int*   ei    = (const int*)  d_in[1];
    const float* ea    = (const float*)d_in[2];
    const int*   batch = (const int*)  d_in[3];
    const float* W1    = (const float*)d_in[4];
    const float* b1    = (const float*)d_in[5];
    const float* W2    = (const float*)d_in[6];
    const float* b2    = (const float*)d_in[7];
    const float* W3    = (const float*)d_in[8];
    const float* b3    = (const float*)d_in[9];
    const float* gamma = (const float*)d_in[10];
    const float* beta  = (const float*)d_in[11];
    const float* Wm1   = (const float*)d_in[12];
    const float* bm1   = (const float*)d_in[13];
    const float* Wm2   = (const float*)d_in[14];
    const float* bm2   = (const float*)d_in[15];
    float* out = (float*)d_out;

    const int* src = ei;
    const int* dst = ei + EE;

    cudaFuncSetAttribute(gemm_mma_kernel, cudaFuncAttributeMaxDynamicSharedMemorySize, SM_TOTAL);

    void* hbuf_ptr = nullptr;
    cudaGetSymbolAddress(&hbuf_ptr, g_hbuf);

    init_kernel<<<(NN + 255) / 256, 256>>>();
    deg_kernel<<<(EE + 255) / 256, 256>>>(dst, ea);
    wconv_kernel<<<(3 * CH * CH / 2 + 255) / 256, 256>>>(W1, W2, W3);
    blocksum_kernel<<<NBLK, SCAN_BLK>>>();
    bscan_kernel<<<1, 128>>>();
    rowptr_kernel<<<NBLK, SCAN_BLK>>>(batch);
    fill_kernel<<<(EE + 255) / 256, 256>>>(src, dst, ea);

    const float* bs[3] = {b1, b2, b3};
    const float* inp = x;
    for (int l = 0; l < 3; l++) {
        gemm_mma_kernel<<<(NN + 127) / 128, 256, SM_TOTAL>>>(inp, l);
        agg_kernel<<<(int)(((long long)NN * 32 + 255) / 256), 256>>>(bs[l]);
        inp = (const float*)hbuf_ptr;
    }

    pool_kernel<<<(NN + NPB - 1) / NPB, CH>>>(batch);
    head_kernel<<<NB, CH>>>(gamma, beta, Wm1, bm1, Wm2, bm2, out);
}

// round 16
// speedup vs baseline: 1.1187x; 1.1187x over previous
#include <cuda_runtime.h>
#include <cuda_bf16.h>

#define NN   50000
#define EE   800000
#define CH   128
#define NB   256
#define NCLS 10
#define MLPH 64
#define EPSV 1e-5f

#define SCAN_BLK 512
#define NBLK ((NN + SCAN_BLK - 1) / SCAN_BLK)   // 98

// padded row length for bf16 W tiles: 136 elements (272B) -> conflict-free ldmatrix
#define LDK 136
#define WIMG_U32 (CH * LDK / 2)

// ---------------- scratch ----------------
__device__ float    g_deg[NN];
__device__ int      g_degcnt[NN];
__device__ int      g_rowptr[NN + 1];
__device__ int      g_woff[NN];
__device__ int      g_bsum[NBLK];
__device__ int      g_boff[NBLK];
__device__ int      g_csr_src[EE];
__device__ float    g_csr_norm[EE];
__device__ float    g_hlin[NN * CH];
__device__ float    g_hbuf[NN * CH];
__device__ float    g_chsum[CH];
__device__ float    g_chsq[CH];
__device__ float    g_gsum[NB * CH];
__device__ float    g_gcnt[NB];
__device__ unsigned g_Wimg_hi[3][WIMG_U32];
__device__ unsigned g_Wimg_lo[3][WIMG_U32];

// ---------------- mma helpers ----------------
__device__ __forceinline__ unsigned smem_u32(const void* p) {
    unsigned a;
    asm("{ .reg .u64 t; cvta.to.shared.u64 t, %1; cvt.u32.u64 %0, t; }" : "=r"(a) : "l"(p));
    return a;
}
__device__ __forceinline__ void ldsm_x4(unsigned* r, unsigned addr) {
    asm volatile("ldmatrix.sync.aligned.m8n8.x4.shared.b16 {%0,%1,%2,%3}, [%4];"
                 : "=r"(r[0]), "=r"(r[1]), "=r"(r[2]), "=r"(r[3]) : "r"(addr));
}
__device__ __forceinline__ void mma16816(float* c, const unsigned* a, unsigned b0, unsigned b1) {
    asm volatile(
        "mma.sync.aligned.m16n8k16.row.col.f32.bf16.bf16.f32 "
        "{%0,%1,%2,%3}, {%4,%5,%6,%7}, {%8,%9}, {%0,%1,%2,%3};"
        : "+f"(c[0]), "+f"(c[1]), "+f"(c[2]), "+f"(c[3])
        : "r"(a[0]), "r"(a[1]), "r"(a[2]), "r"(a[3]), "r"(b0), "r"(b1));
}
__device__ __forceinline__ unsigned pack_bf16_hi(float a0, float a1, unsigned* lo) {
    __nv_bfloat16 h0 = __float2bfloat16(a0);
    __nv_bfloat16 h1 = __float2bfloat16(a1);
    __nv_bfloat16 l0 = __float2bfloat16(a0 - __bfloat162float(h0));
    __nv_bfloat16 l1 = __float2bfloat16(a1 - __bfloat162float(h1));
    *lo = (unsigned)__bfloat16_as_ushort(l0) | ((unsigned)__bfloat16_as_ushort(l1) << 16);
    return (unsigned)__bfloat16_as_ushort(h0) | ((unsigned)__bfloat16_as_ushort(h1) << 16);
}

// SMEM: W hi + W lo only
#define TILE_B (CH * LDK * 2)
#define SM_WHI 0
#define SM_WLO TILE_B
#define SM_TOTAL (2 * TILE_B)

// ---------------- W split precompute, all 3 layers in one launch ----------------
__global__ void wconv_kernel(const float* __restrict__ W1, const float* __restrict__ W2,
                             const float* __restrict__ W3) {
    int g = blockIdx.x * blockDim.x + threadIdx.x;
    int layer = g / (CH * CH / 2);
    int r = g % (CH * CH / 2);
    if (layer >= 3) return;
    const float* W = (layer == 0) ? W1 : (layer == 1) ? W2 : W3;
    int n = r >> 6;
    int kp = (r & 63) * 2;
    float a0 = W[kp * CH + n];
    float a1 = W[(kp + 1) * CH + n];
    unsigned lo;
    unsigned hi = pack_bf16_hi(a0, a1, &lo);
    int idx = (n * LDK + kp) / 2;
    g_Wimg_hi[layer][idx] = hi;
    g_Wimg_lo[layer][idx] = lo;
}

// ---------------- HMMA GEMM: 128x128 tile/CTA, A fragments direct from global ----------------
__global__ void __launch_bounds__(256, 2) gemm_mma_kernel(const float* __restrict__ A, int layer) {
    extern __shared__ char smem[];
    unsigned sb = smem_u32(smem);
    int tid = threadIdx.x;
    int wid = tid >> 5;
    int lane = tid & 31;
    int row0 = blockIdx.x * 128;

    // copy W images into SMEM
    {
        const uint4* wh = (const uint4*)g_Wimg_hi[layer];
        const uint4* wl = (const uint4*)g_Wimg_lo[layer];
        for (int i = tid; i < TILE_B / 16; i += 256) {
            *(uint4*)(smem + SM_WHI + i * 16) = wh[i];
            *(uint4*)(smem + SM_WLO + i * 16) = wl[i];
        }
    }
    __syncthreads();

    int wm0 = (wid >> 1) * 32;       // warp M offset (within 128)
    int wn0 = (wid & 1) * 64;        // warp N offset

    float c[2][8][4];
#pragma unroll
    for (int mt = 0; mt < 2; mt++)
#pragma unroll
        for (int nt = 0; nt < 8; nt++)
#pragma unroll
            for (int j = 0; j < 4; j++) c[mt][nt][j] = 0.f;

    // A-fragment lane coords (m16n8k16 row-major A)
    int fr = lane >> 2;              // 0..7
    int fc = (lane & 3) * 2;         // 0,2,4,6
    // B ldmatrix coords
    int rsel = lane & 15;
    int ksel = (lane >> 4) * 8;

#pragma unroll 2
    for (int ch = 0; ch < 8; ch++) {
        int k0 = ch * 16;
        unsigned ahi[2][4], alo[2][4];
#pragma unroll
        for (int mt = 0; mt < 2; mt++) {
            int rA = row0 + wm0 + mt * 16 + fr;     // rows rA, rA+8
            float2 v0 = make_float2(0.f, 0.f), v1 = v0, v2 = v0, v3 = v0;
            if (rA < NN)     { v0 = *(const float2*)&A[rA * CH + k0 + fc];
                               v2 = *(const float2*)&A[rA * CH + k0 + fc + 8]; }
            if (rA + 8 < NN) { v1 = *(const float2*)&A[(rA + 8) * CH + k0 + fc];
                               v3 = *(const float2*)&A[(rA + 8) * CH + k0 + fc + 8]; }
            ahi[mt][0] = pack_bf16_hi(v0.x, v0.y, &alo[mt][0]);
            ahi[mt][1] = pack_bf16_hi(v1.x, v1.y, &alo[mt][1]);
            ahi[mt][2] = pack_bf16_hi(v2.x, v2.y, &alo[mt][2]);
            ahi[mt][3] = pack_bf16_hi(v3.x, v3.y, &alo[mt][3]);
        }
#pragma unroll
        for (int nb = 0; nb < 4; nb++) {
            unsigned baddr = sb + SM_WHI + ((wn0 + nb * 16 + rsel) * LDK + k0 + ksel) * 2;
            unsigned bh[4], bl[4];
            ldsm_x4(bh, baddr);
            ldsm_x4(bl, baddr + (SM_WLO - SM_WHI));
#pragma unroll
            for (int mt = 0; mt < 2; mt++) {
                mma16816(c[mt][nb * 2],     ahi[mt], bh[0], bh[2]);
                mma16816(c[mt][nb * 2],     alo[mt], bh[0], bh[2]);
                mma16816(c[mt][nb * 2],     ahi[mt], bl[0], bl[2]);
                mma16816(c[mt][nb * 2 + 1], ahi[mt], bh[1], bh[3]);
                mma16816(c[mt][nb * 2 + 1], alo[mt], bh[1], bh[3]);
                mma16816(c[mt][nb * 2 + 1], ahi[mt], bl[1], bl[3]);
            }
        }
    }

    int lrow = lane >> 2;
    int lcol = (lane & 3) * 2;
#pragma unroll
    for (int mt = 0; mt < 2; mt++) {
        int r1 = row0 + wm0 + mt * 16 + lrow;
        int r2 = r1 + 8;
#pragma unroll
        for (int nt = 0; nt < 8; nt++) {
            int col = wn0 + nt * 8 + lcol;
            if (r1 < NN) *(float2*)&g_hlin[r1 * CH + col] = make_float2(c[mt][nt][0], c[mt][nt][1]);
            if (r2 < NN) *(float2*)&g_hlin[r2 * CH + col] = make_float2(c[mt][nt][2], c[mt][nt][3]);
        }
    }
}

// ---------------- init ----------------
__global__ void init_kernel() {
    int i = blockIdx.x * blockDim.x + threadIdx.x;
    if (i < NN) { g_deg[i] = 1.0f; g_degcnt[i] = 0; }
    if (i < CH) { g_chsum[i] = 0.f; g_chsq[i] = 0.f; }
    if (i < NB * CH) g_gsum[i] = 0.f;
    if (i < NB) g_gcnt[i] = 0.f;
}

__global__ void deg_kernel(const int* __restrict__ dst, const float* __restrict__ ew) {
    int e = blockIdx.x * blockDim.x + threadIdx.x;
    if (e < EE) {
        int d = dst[e];
        atomicAdd(&g_deg[d], ew[e]);
        atomicAdd(&g_degcnt[d], 1);
    }
}

// blocksum + dinv fused
__global__ void blocksum_kernel() {
    __shared__ int ws[SCAN_BLK / 32];
    int t = threadIdx.x;
    int i = blockIdx.x * SCAN_BLK + t;
    if (i < NN) g_deg[i] = rsqrtf(g_deg[i]);
    int v = (i < NN) ? g_degcnt[i] : 0;
#pragma unroll
    for (int o = 16; o > 0; o >>= 1) v += __shfl_down_sync(0xffffffffu, v, o);
    if ((t & 31) == 0) ws[t >> 5] = v;
    __syncthreads();
    if (t < 32) {
        int s = (t < SCAN_BLK / 32) ? ws[t] : 0;
#pragma unroll
        for (int o = 16; o > 0; o >>= 1) s += __shfl_down_sync(0xffffffffu, s, o);
        if (t == 0) g_bsum[blockIdx.x] = s;
    }
}

__global__ void bscan_kernel() {
    __shared__ int sh[128];
    int t = threadIdx.x;
    sh[t] = (t < NBLK) ? g_bsum[t] : 0;
    __syncthreads();
#pragma unroll
    for (int o = 1; o < 128; o <<= 1) {
        int v = (t >= o) ? sh[t - o] : 0;
        __syncthreads();
        sh[t] += v;
        __syncthreads();
    }
    if (t < NBLK) g_boff[t] = sh[t] - g_bsum[t];
}

// rowptr + per-graph count fused
__global__ void rowptr_kernel(const int* __restrict__ batch) {
    __shared__ int ws[SCAN_BLK / 32];
    int t = threadIdx.x;
    int i = blockIdx.x * SCAN_BLK + t;
    if (i < NN) atomicAdd(&g_gcnt[batch[i]], 1.0f);
    int v = (i < NN) ? g_degcnt[i] : 0;
    int lane = t & 31;
    int wid = t >> 5;
    int sc = v;
#pragma unroll
    for (int o = 1; o < 32; o <<= 1) {
        int u = __shfl_up_sync(0xffffffffu, sc, o);
        if (lane >= o) sc += u;
    }
    if (lane == 31) ws[wid] = sc;
    __syncthreads();
    if (t < 32) {
        int s = (t < SCAN_BLK / 32) ? ws[t] : 0;
#pragma unroll
        for (int o = 1; o < 32; o <<= 1) {
            int u = __shfl_up_sync(0xffffffffu, s, o);
            if ((t & 31) >= o) s += u;
        }
        if (t < SCAN_BLK / 32) ws[t] = s;
    }
    __syncthreads();
    int excl = sc - v + ((wid > 0) ? ws[wid - 1] : 0) + g_boff[blockIdx.x];
    if (i < NN) { g_rowptr[i] = excl; g_woff[i] = excl; }
    if (i == NN - 1) g_rowptr[NN] = EE;
}

__global__ void fill_kernel(const int* __restrict__ src, const int* __restrict__ dst,
                            const float* __restrict__ ew) {
    int e = blockIdx.x * blockDim.x + threadIdx.x;
    if (e >= EE) return;
    int s = src[e];
    int d = dst[e];
    float nm = g_deg[s] * ew[e] * g_deg[d];
    int pos = atomicAdd(&g_woff[d], 1);
    g_csr_src[pos] = s;
    g_csr_norm[pos] = nm;
}

// ---------------- aggregation: warp per dst node (R12 form) ----------------
__global__ void agg_kernel(const float* __restrict__ bias) {
    int gid = blockIdx.x * blockDim.x + threadIdx.x;
    int n = gid >> 5;
    if (n >= NN) return;
    int lane = gid & 31;

    float di = g_deg[n];
    float d2 = di * di;
    float4 self = *(const float4*)&g_hlin[n * CH + lane * 4];
    float4 acc = make_float4(self.x * d2, self.y * d2, self.z * d2, self.w * d2);

    int beg = g_rowptr[n];
    int end = g_rowptr[n + 1];
#pragma unroll 2
    for (int p = beg; p < end; p++) {
        int s = __ldg(&g_csr_src[p]);
        float nm = __ldg(&g_csr_norm[p]);
        float4 v = *(const float4*)&g_hlin[s * CH + lane * 4];
        acc.x += nm * v.x;
        acc.y += nm * v.y;
        acc.z += nm * v.z;
        acc.w += nm * v.w;
    }

    float4 b = *(const float4*)&bias[lane * 4];
    float4 r;
    r.x = fmaxf(acc.x + b.x, 0.f);
    r.y = fmaxf(acc.y + b.y, 0.f);
    r.z = fmaxf(acc.z + b.z, 0.f);
    r.w = fmaxf(acc.w + b.w, 0.f);
    *(float4*)&g_hbuf[n * CH + lane * 4] = r;
}

// ---------------- BN stats + pooled sums ----------------
#define NPB 256
__global__ void pool_kernel(const int* __restrict__ batch) {
    int c = threadIdx.x;
    int n0 = blockIdx.x * NPB;
    int nend = min(n0 + NPB, NN);
    if (n0 >= NN) return;
    float s = 0.f, sq = 0.f, loc = 0.f;
    int curg = __ldg(&batch[n0]);
    for (int n = n0; n < nend; n++) {
        float v = g_hbuf[n * CH + c];
        s += v; sq += v * v;
        int g = __ldg(&batch[n]);
        if (g != curg) {
            atomicAdd(&g_gsum[curg * CH + c], loc);
            loc = 0.f;
            curg = g;
        }
        loc += v;
    }
    atomicAdd(&g_gsum[curg * CH + c], loc);
    atomicAdd(&g_chsum[c], s);
    atomicAdd(&g_chsq[c], sq);
}

// ---------------- head ----------------
__global__ void head_kernel(const float* __restrict__ gamma, const float* __restrict__ beta,
                            const float* __restrict__ Wm1, const float* __restrict__ bm1,
                            const float* __restrict__ Wm2, const float* __restrict__ bm2,
                            float* __restrict__ out) {
    __shared__ float gs[CH];
    __shared__ float tt[MLPH];
    int b = blockIdx.x;
    int c = threadIdx.x;
    float mu = g_chsum[c] * (1.0f / NN);
    float var = g_chsq[c] * (1.0f / NN) - mu * mu;
    float rs = rsqrtf(var + EPSV);
    float cnt = fmaxf(g_gcnt[b], 1.0f);
    gs[c] = (g_gsum[b * CH + c] / cnt - mu) * rs * gamma[c] + beta[c];
    __syncthreads();
    if (c < MLPH) {
        float acc = bm1[c];
#pragma unroll 8
        for (int k = 0; k < CH; k++) acc += gs[k] * Wm1[k * MLPH + c];
        tt[c] = acc;
    }
    __syncthreads();
    if (c < NCLS) {
        float acc = bm2[c];
#pragma unroll 8
        for (int k = 0; k < MLPH; k++) acc += tt[k] * Wm2[k * NCLS + c];
        out[b * NCLS + c] = acc;
    }
}

// ---------------- launch ----------------
extern "C" void kernel_launch(void* const* d_in, const int* in_sizes, int n_in,
                              void* d_out, int out_size) {
    const float* x     = (const float*)d_in[0];
    const int*   ei    = (const int*)  d_in[1];
    const float* ea    = (const float*)d_in[2];
    const int*   batch = (const int*)  d_in[3];
    const float* W1    = (const float*)d_in[4];
    const float* b1    = (const float*)d_in[5];
    const float* W2    = (const float*)d_in[6];
    const float* b2    = (const float*)d_in[7];
    const float* W3    = (const float*)d_in[8];
    const float* b3    = (const float*)d_in[9];
    const float* gamma = (const float*)d_in[10];
    const float* beta  = (const float*)d_in[11];
    const float* Wm1   = (const float*)d_in[12];
    const float* bm1   = (const float*)d_in[13];
    const float* Wm2   = (const float*)d_in[14];
    const float* bm2   = (const float*)d_in[15];
    float* out = (float*)d_out;

    const int* src = ei;
    const int* dst = ei + EE;

    cudaFuncSetAttribute(gemm_mma_kernel, cudaFuncAttributeMaxDynamicSharedMemorySize, SM_TOTAL);

    void* hbuf_ptr = nullptr;
    cudaGetSymbolAddress(&hbuf_ptr, g_hbuf);

    init_kernel<<<(NN + 255) / 256, 256>>>();
    deg_kernel<<<(EE + 255) / 256, 256>>>(dst, ea);
    wconv_kernel<<<(3 * CH * CH / 2 + 255) / 256, 256>>>(W1, W2, W3);
    blocksum_kernel<<<NBLK, SCAN_BLK>>>();
    bscan_kernel<<<1, 128>>>();
    rowptr_kernel<<<NBLK, SCAN_BLK>>>(batch);
    fill_kernel<<<(EE + 255) / 256, 256>>>(src, dst, ea);

    const float* bs[3] = {b1, b2, b3};
    const float* inp = x;
    for (int l = 0; l < 3; l++) {
        gemm_mma_kernel<<<(NN + 127) / 128, 256, SM_TOTAL>>>(inp, l);
        agg_kernel<<<(int)(((long long)NN * 32 + 255) / 256), 256>>>(bs[l]);
        inp = (const float*)hbuf_ptr;
    }

    pool_kernel<<<(NN + NPB - 1) / NPB, CH>>>(batch);
    head_kernel<<<NB, CH>>>(gamma, beta, Wm1, bm1, Wm2, bm2, out);
}